// round 12
// baseline (speedup 1.0000x reference)
#include <cuda_runtime.h>
#include <cuda_bf16.h>
#include <math.h>
#include <stdint.h>

// Model dims
#define QL 512
#define BS 8
#define VC 32000
#define DM 1024
#define NH 16
#define DHD 64
#define FFD 4096
#define NL 4
#define RL 513
#define TOK 4096
#define BH 128
#define ATT_SCALE 0.125f

// ---------------------------------------------------------------------------
// Scratch
// ---------------------------------------------------------------------------
__device__ float g_core[TOK * DM];
__device__ float g_big[TOK * FFD];          // QKV output fp32 (read by prep)
__device__ float g_vec[TOK * DM];           // src2 scratch
__device__ float g_tmp[TOK * DM];
__device__ float g_h[TOK * DM];
__device__ float g_r[RL * DM];
__device__ float g_rqkv[RL * 3 * DM];
__device__ float g_qr[(size_t)BH * QL * RL];     // BD pre-shift fp32
__device__ float g_score[(size_t)BH * QL * QL];  // pre-softmax scores fp32
// split-bf16 buffers (hi/lo)
__device__ __nv_bfloat16 g_ah[TOK * FFD];        // FFN1 output split
__device__ __nv_bfloat16 g_al[TOK * FFD];
__device__ __nv_bfloat16 g_wh[DM * FFD];         // weight split
__device__ __nv_bfloat16 g_wl[DM * FFD];
__device__ __nv_bfloat16 g_eh[(size_t)VC * DM];  // embedding split
__device__ __nv_bfloat16 g_el[(size_t)VC * DM];
__device__ __nv_bfloat16 g_ch[TOK * DM];         // core split
__device__ __nv_bfloat16 g_cl[TOK * DM];
__device__ __nv_bfloat16 g_vh[TOK * DM];         // attn-out split (Wo input)
__device__ __nv_bfloat16 g_vl[TOK * DM];
__device__ __nv_bfloat16 g_hsh[TOK * DM];        // h split (FFN1 input)
__device__ __nv_bfloat16 g_hsl[TOK * DM];
// per-head attention operands [bn][512][64]
__device__ __nv_bfloat16 g_qh[(size_t)BH * QL * DHD], g_ql[(size_t)BH * QL * DHD];
__device__ __nv_bfloat16 g_kh[(size_t)BH * QL * DHD], g_kl[(size_t)BH * QL * DHD];
__device__ __nv_bfloat16 g_uh[(size_t)BH * QL * DHD], g_ul[(size_t)BH * QL * DHD];
__device__ __nv_bfloat16 g_rkh[NH * RL * DHD], g_rkl[NH * RL * DHD];
// split probabilities [bn][512][512]
__device__ __nv_bfloat16 g_ph[(size_t)BH * QL * QL], g_pl[(size_t)BH * QL * QL];

static __device__ __forceinline__ uint32_t s2u(const void* p) {
    return (uint32_t)__cvta_generic_to_shared(p);
}

#define LDSM4(R, addr)                                                           \
    asm volatile("ldmatrix.sync.aligned.m8n8.x4.shared.b16 {%0,%1,%2,%3}, [%4];" \
                 : "=r"(R[0]), "=r"(R[1]), "=r"(R[2]), "=r"(R[3]) : "r"(addr));
#define LDSM4T(R, addr)                                                                \
    asm volatile("ldmatrix.sync.aligned.m8n8.x4.trans.shared.b16 {%0,%1,%2,%3}, [%4];" \
                 : "=r"(R[0]), "=r"(R[1]), "=r"(R[2]), "=r"(R[3]) : "r"(addr));
#define MMA_BF16(ac, A, b0, b1)                                                  \
    asm volatile("mma.sync.aligned.m16n8k16.row.col.f32.bf16.bf16.f32 "          \
                 "{%0,%1,%2,%3}, {%4,%5,%6,%7}, {%8,%9}, {%0,%1,%2,%3};"         \
                 : "+f"(ac[0]), "+f"(ac[1]), "+f"(ac[2]), "+f"(ac[3])            \
                 : "r"(A[0]), "r"(A[1]), "r"(A[2]), "r"(A[3]), "r"(b0), "r"(b1));

static __device__ __forceinline__ void cp16(__nv_bfloat16* dst,
                                            const __nv_bfloat16* src, bool pred) {
    uint32_t d = s2u(dst);
    int n = pred ? 16 : 0;
    asm volatile("cp.async.cg.shared.global [%0], [%1], 16, %2;" ::"r"(d), "l"(src), "r"(n));
}

static __device__ __forceinline__ void split1(float v, __nv_bfloat16& hi, __nv_bfloat16& lo) {
    hi = __float2bfloat16(v);
    lo = __float2bfloat16(v - __bfloat162float(hi));
}

static __device__ __forceinline__ void split_store4(float x0, float x1, float x2, float x3,
                                                    __nv_bfloat16* H, __nv_bfloat16* L) {
    __nv_bfloat16 h0, h1, h2, h3, l0, l1, l2, l3;
    split1(x0, h0, l0); split1(x1, h1, l1);
    split1(x2, h2, l2); split1(x3, h3, l3);
    *(__nv_bfloat162*)(H)     = __nv_bfloat162(h0, h1);
    *(__nv_bfloat162*)(H + 2) = __nv_bfloat162(h2, h3);
    *(__nv_bfloat162*)(L)     = __nv_bfloat162(l0, l1);
    *(__nv_bfloat162*)(L + 2) = __nv_bfloat162(l2, l3);
}

// ---------------------------------------------------------------------------
// Split fp32 -> (hi, lo) bf16 (weights / embedding)
// ---------------------------------------------------------------------------
__global__ void k_split(const float* __restrict__ x, __nv_bfloat16* __restrict__ h,
                        __nv_bfloat16* __restrict__ l, int n) {
    int i = (blockIdx.x * 256 + threadIdx.x) * 4;
    if (i >= n) return;
    float4 v = *(const float4*)(x + i);
    split_store4(v.x, v.y, v.z, v.w, h + i, l + i);
}

// ---------------------------------------------------------------------------
// Split-bf16 tensor-core GEMM, 2-stage cp.async pipeline.
// ---------------------------------------------------------------------------
template <int ACT, bool TB, bool SPLIT_OUT>
__global__ __launch_bounds__(256, 2)
void k_mgemm(const __nv_bfloat16* __restrict__ Ah, const __nv_bfloat16* __restrict__ Al,
             const __nv_bfloat16* __restrict__ Bh, const __nv_bfloat16* __restrict__ Bl,
             const float* __restrict__ bias, float* __restrict__ C,
             __nv_bfloat16* __restrict__ Oh, __nv_bfloat16* __restrict__ Ol,
             int M, int N, int K) {
    constexpr int BSTR = TB ? 40 : 136;
    constexpr int ASTG = 128 * 40;
    constexpr int BSTG = TB ? 128 * 40 : 32 * 136;
    constexpr int STG = 2 * ASTG + 2 * BSTG;
    extern __shared__ __nv_bfloat16 smem[];

    int tid = threadIdx.x;
    int m0 = blockIdx.y << 7, n0 = blockIdx.x << 7;
    int lane = tid & 31, warp = tid >> 5;
    int wm = warp >> 1, wn = warp & 1;

    float acc[2][8][4];
#pragma unroll
    for (int a = 0; a < 2; a++)
#pragma unroll
        for (int b = 0; b < 8; b++)
#pragma unroll
            for (int c = 0; c < 4; c++) acc[a][b][c] = 0.f;

    auto load_stage = [&](int k0, int s) {
        __nv_bfloat16* sAh = smem + s * STG;
        __nv_bfloat16* sAl = sAh + ASTG;
        __nv_bfloat16* sBh = sAl + ASTG;
        __nv_bfloat16* sBl = sBh + BSTG;
#pragma unroll
        for (int u = 0; u < 2; u++) {
            int p = tid + u * 256;
            int row = p >> 2, kq = (p & 3) << 3;
            bool ok = (m0 + row) < M;
            size_t off = (size_t)(m0 + row) * K + k0 + kq;
            cp16(&sAh[row * 40 + kq], Ah + off, ok);
            cp16(&sAl[row * 40 + kq], Al + off, ok);
        }
#pragma unroll
        for (int u = 0; u < 2; u++) {
            int p = tid + u * 256;
            if (TB) {
                int row = p >> 2, kq = (p & 3) << 3;
                size_t off = (size_t)(n0 + row) * K + k0 + kq;
                cp16(&sBh[row * 40 + kq], Bh + off, true);
                cp16(&sBl[row * 40 + kq], Bl + off, true);
            } else {
                int row = p >> 4, nq = (p & 15) << 3;
                size_t off = (size_t)(k0 + row) * N + n0 + nq;
                cp16(&sBh[row * 136 + nq], Bh + off, true);
                cp16(&sBl[row * 136 + nq], Bl + off, true);
            }
        }
        asm volatile("cp.async.commit_group;");
    };

    int KT = K >> 5;
    load_stage(0, 0);

    for (int kt = 0; kt < KT; kt++) {
        if (kt + 1 < KT) load_stage((kt + 1) << 5, (kt + 1) & 1);
        else asm volatile("cp.async.commit_group;");
        asm volatile("cp.async.wait_group 1;");
        __syncthreads();

        const __nv_bfloat16* sAh = smem + (kt & 1) * STG;
        const __nv_bfloat16* sAl = sAh + ASTG;
        const __nv_bfloat16* sBh = sAl + ASTG;
        const __nv_bfloat16* sBl = sBh + BSTG;

#pragma unroll
        for (int ks = 0; ks < 32; ks += 16) {
            uint32_t ah[2][4], al[2][4];
#pragma unroll
            for (int mt = 0; mt < 2; mt++) {
                int rb = wm * 32 + mt * 16 + (lane & 15);
                int kc = ks + ((lane >> 4) << 3);
                LDSM4(ah[mt], s2u(&sAh[rb * 40 + kc]));
                LDSM4(al[mt], s2u(&sAl[rb * 40 + kc]));
            }
#pragma unroll
            for (int np = 0; np < 4; np++) {
                int nb = wn * 64 + np * 16;
                uint32_t bh[4], bl[4];
                int g = lane >> 3, l8 = lane & 7;
                if (TB) {
                    int nr = nb + ((g >> 1) << 3) + l8;
                    int kc = ks + ((g & 1) << 3);
                    LDSM4(bh, s2u(&sBh[nr * BSTR + kc]));
                    LDSM4(bl, s2u(&sBl[nr * BSTR + kc]));
                } else {
                    int kr = ks + ((g & 1) << 3) + l8;
                    int nc = nb + ((g >> 1) << 3);
                    LDSM4T(bh, s2u(&sBh[kr * BSTR + nc]));
                    LDSM4T(bl, s2u(&sBl[kr * BSTR + nc]));
                }
#pragma unroll
                for (int mt = 0; mt < 2; mt++) {
#pragma unroll
                    for (int j = 0; j < 2; j++) {
                        float* ac = acc[mt][np * 2 + j];
                        MMA_BF16(ac, ah[mt], bh[2 * j], bh[2 * j + 1]);
                        MMA_BF16(ac, ah[mt], bl[2 * j], bl[2 * j + 1]);
                        MMA_BF16(ac, al[mt], bh[2 * j], bh[2 * j + 1]);
                    }
                }
            }
        }
        __syncthreads();
    }

#pragma unroll
    for (int mt = 0; mt < 2; mt++) {
#pragma unroll
        for (int np = 0; np < 4; np++) {
#pragma unroll
            for (int j = 0; j < 2; j++) {
                int nt = np * 2 + j;
                int col = n0 + wn * 64 + np * 16 + j * 8 + (lane & 3) * 2;
                int rb = m0 + wm * 32 + mt * 16 + (lane >> 2);
#pragma unroll
                for (int hh = 0; hh < 2; hh++) {
                    int r = rb + hh * 8;
                    if (r >= M) continue;
                    float v0 = acc[mt][nt][hh * 2];
                    float v1 = acc[mt][nt][hh * 2 + 1];
                    if (bias) { v0 += bias[col]; v1 += bias[col + 1]; }
                    if (ACT == 1) {
                        v0 = 0.5f * v0 * (1.f + erff(v0 * 0.70710678118654752f));
                        v1 = 0.5f * v1 * (1.f + erff(v1 * 0.70710678118654752f));
                    }
                    if (SPLIT_OUT) {
                        __nv_bfloat16 h0, h1, l0, l1;
                        split1(v0, h0, l0);
                        split1(v1, h1, l1);
                        *(__nv_bfloat162*)(Oh + (size_t)r * N + col) = __nv_bfloat162(h0, h1);
                        *(__nv_bfloat162*)(Ol + (size_t)r * N + col) = __nv_bfloat162(l0, l1);
                    } else {
                        *(float2*)(C + (size_t)r * N + col) = make_float2(v0, v1);
                    }
                }
            }
        }
    }
}

// ---------------------------------------------------------------------------
// Embedding lookup * sqrt(D) + fused core split
// ---------------------------------------------------------------------------
__global__ void k_embed(const int* __restrict__ src, const float* __restrict__ emb) {
    int t = blockIdx.x;
    int tok = src[t];
    const float4* e = (const float4*)(emb + (size_t)tok * DM);
    size_t base = (size_t)t * DM;
    for (int d = threadIdx.x; d < DM / 4; d += blockDim.x) {
        float4 v = e[d];
        v.x *= 32.f; v.y *= 32.f; v.z *= 32.f; v.w *= 32.f;
        *(float4*)(g_core + base + d * 4) = v;
        split_store4(v.x, v.y, v.z, v.w, g_ch + base + d * 4, g_cl + base + d * 4);
    }
}

__global__ void k_posemb() {
    int p = blockIdx.x;
    double pos = (double)(QL - p);
    for (int d = threadIdx.x; d < DM; d += blockDim.x) {
        int j = d & 511;
        double inv = exp(-((double)(2 * j) / (double)DM) * log(10000.0));
        double a = pos * inv;
        g_r[p * DM + d] = (d < 512) ? (float)sin(a) : (float)cos(a);
    }
}

// ---------------------------------------------------------------------------
// Prep: QKV fp32 -> per-head split bf16 (Q gets +rq_last in fp32 first)
// ---------------------------------------------------------------------------
__global__ void k_qkvprep() {
    int e = (blockIdx.x * 256 + threadIdx.x) * 4;   // < 4096*3072
    int r = e / (3 * DM);
    int col = e % (3 * DM);
    float4 v = *(const float4*)(g_big + (size_t)r * (3 * DM) + col);
    int part = col >> 10;
    int cl = col & 1023;
    if (part == 0) {
        const float* rql = g_rqkv + (size_t)QL * (3 * DM);
        v.x += rql[cl]; v.y += rql[cl + 1]; v.z += rql[cl + 2]; v.w += rql[cl + 3];
    }
    int n = cl >> 6, d = cl & 63;
    int i = r >> 3, b = r & 7;
    int bn = b * 16 + n;
    size_t dst = ((size_t)bn * QL + i) * DHD + d;
    __nv_bfloat16 *H, *L;
    if (part == 0)      { H = g_qh; L = g_ql; }
    else if (part == 1) { H = g_kh; L = g_kl; }
    else                { H = g_uh; L = g_ul; }
    split_store4(v.x, v.y, v.z, v.w, H + dst, L + dst);
}

// rk part of rqkv -> per-head split bf16 [n][RL][64]
__global__ void k_rkprep() {
    int e = (blockIdx.x * 256 + threadIdx.x) * 4;   // < 513*1024
    if (e >= RL * DM) return;
    int jr = e / DM;
    int c = e % DM;
    int n = c >> 6, d = c & 63;
    float4 v = *(const float4*)(g_rqkv + (size_t)jr * (3 * DM) + DM + c);
    size_t dst = ((size_t)n * RL + jr) * DHD + d;
    split_store4(v.x, v.y, v.z, v.w, g_rkh + dst, g_rkl + dst);
}

// ---------------------------------------------------------------------------
// qr[bn,i,jr] = q_bias . rk  (tensor core, 128x128 tiles, K=64)
// grid (5, 4, 128); only rel-shift-reachable tiles computed
// ---------------------------------------------------------------------------
__global__ __launch_bounds__(256) void k_qrmma() {
    int bn = blockIdx.z, n = bn & 15;
    int i0 = blockIdx.y << 7, jr0 = blockIdx.x << 7;
    if (jr0 + i0 < 258) return;   // tile never gathered by rel-shift
    extern __shared__ __nv_bfloat16 sm[];
    __nv_bfloat16 *sQh = sm, *sQl = sm + 128 * 72, *sKh = sm + 2 * 128 * 72,
                  *sKl = sm + 3 * 128 * 72;
    int tid = threadIdx.x, lane = tid & 31, warp = tid >> 5;
    int wm = warp >> 1, wn = warp & 1;

    const __nv_bfloat16* qh = g_qh + ((size_t)bn * QL + i0) * DHD;
    const __nv_bfloat16* ql = g_ql + ((size_t)bn * QL + i0) * DHD;
    const __nv_bfloat16* rh = g_rkh + ((size_t)n * RL + jr0) * DHD;
    const __nv_bfloat16* rl = g_rkl + ((size_t)n * RL + jr0) * DHD;
#pragma unroll
    for (int u = 0; u < 4; u++) {
        int p = tid + u * 256;
        int row = p >> 3, q8 = (p & 7) << 3;
        bool ok = (jr0 + row) < RL;
        cp16(&sQh[row * 72 + q8], qh + row * 64 + q8, true);
        cp16(&sQl[row * 72 + q8], ql + row * 64 + q8, true);
        cp16(&sKh[row * 72 + q8], rh + row * 64 + q8, ok);
        cp16(&sKl[row * 72 + q8], rl + row * 64 + q8, ok);
    }
    asm volatile("cp.async.commit_group;");
    asm volatile("cp.async.wait_group 0;");
    __syncthreads();

    float acc[2][8][4];
#pragma unroll
    for (int a = 0; a < 2; a++)
#pragma unroll
        for (int b = 0; b < 8; b++)
#pragma unroll
            for (int c = 0; c < 4; c++) acc[a][b][c] = 0.f;

#pragma unroll
    for (int ks = 0; ks < 64; ks += 16) {
        uint32_t ah[2][4], al[2][4];
#pragma unroll
        for (int mt = 0; mt < 2; mt++) {
            int rb = wm * 32 + mt * 16 + (lane & 15);
            int kc = ks + ((lane >> 4) << 3);
            LDSM4(ah[mt], s2u(&sQh[rb * 72 + kc]));
            LDSM4(al[mt], s2u(&sQl[rb * 72 + kc]));
        }
        int g = lane >> 3, l8 = lane & 7;
#pragma unroll
        for (int np = 0; np < 4; np++) {
            int nb = wn * 64 + np * 16;
            uint32_t bh[4], bl[4];
            int nr = nb + ((g >> 1) << 3) + l8;
            int kc = ks + ((g & 1) << 3);
            LDSM4(bh, s2u(&sKh[nr * 72 + kc]));
            LDSM4(bl, s2u(&sKl[nr * 72 + kc]));
#pragma unroll
            for (int mt = 0; mt < 2; mt++) {
#pragma unroll
                for (int j = 0; j < 2; j++) {
                    float* ac = acc[mt][np * 2 + j];
                    MMA_BF16(ac, ah[mt], bh[2 * j], bh[2 * j + 1]);
                    MMA_BF16(ac, ah[mt], bl[2 * j], bl[2 * j + 1]);
                    MMA_BF16(ac, al[mt], bh[2 * j], bh[2 * j + 1]);
                }
            }
        }
    }

    // NOTE: RL=513 is ODD -> (r*RL + col) parity alternates with r.
    // float2 stores here caused 'misaligned address'; use scalar stores.
    float* out = g_qr + (size_t)bn * QL * RL;
#pragma unroll
    for (int mt = 0; mt < 2; mt++) {
#pragma unroll
        for (int np = 0; np < 4; np++) {
#pragma unroll
            for (int j = 0; j < 2; j++) {
                int col = jr0 + wn * 64 + np * 16 + j * 8 + (lane & 3) * 2;
                int rb = i0 + wm * 32 + mt * 16 + (lane >> 2);
#pragma unroll
                for (int hh = 0; hh < 2; hh++) {
                    int r = rb + hh * 8;
                    float v0 = acc[mt][np * 2 + j][hh * 2];
                    float v1 = acc[mt][np * 2 + j][hh * 2 + 1];
                    if (col < RL)     out[(size_t)r * RL + col] = v0;
                    if (col + 1 < RL) out[(size_t)r * RL + col + 1] = v1;
                }
            }
        }
    }
}

// ---------------------------------------------------------------------------
// score = (Q.K^T + rel_shift(qr)) * SCALE, causal mask. 128x128 tiles.
// grid (4, 4, 128)
// ---------------------------------------------------------------------------
__global__ __launch_bounds__(256) void k_scoremma() {
    int bn = blockIdx.z;
    int i0 = blockIdx.y << 7, j0 = blockIdx.x << 7;
    int tid = threadIdx.x;
    float* srow = g_score + (size_t)bn * QL * QL;
    if (j0 > i0) {   // strictly upper tile: -inf fill
        float4 ninf = make_float4(-INFINITY, -INFINITY, -INFINITY, -INFINITY);
#pragma unroll
        for (int u = 0; u < 16; u++) {
            int p = tid + u * 256;
            int r = p >> 5, c = (p & 31) << 2;
            *(float4*)&srow[(size_t)(i0 + r) * QL + j0 + c] = ninf;
        }
        return;
    }
    extern __shared__ __nv_bfloat16 sm[];
    __nv_bfloat16 *sQh = sm, *sQl = sm + 128 * 72, *sKh = sm + 2 * 128 * 72,
                  *sKl = sm + 3 * 128 * 72;
    int lane = tid & 31, warp = tid >> 5;
    int wm = warp >> 1, wn = warp & 1;

    const __nv_bfloat16* qh = g_qh + ((size_t)bn * QL + i0) * DHD;
    const __nv_bfloat16* ql = g_ql + ((size_t)bn * QL + i0) * DHD;
    const __nv_bfloat16* kh = g_kh + ((size_t)bn * QL + j0) * DHD;
    const __nv_bfloat16* kl = g_kl + ((size_t)bn * QL + j0) * DHD;
#pragma unroll
    for (int u = 0; u < 4; u++) {
        int p = tid + u * 256;
        int row = p >> 3, q8 = (p & 7) << 3;
        cp16(&sQh[row * 72 + q8], qh + row * 64 + q8, true);
        cp16(&sQl[row * 72 + q8], ql + row * 64 + q8, true);
        cp16(&sKh[row * 72 + q8], kh + row * 64 + q8, true);
        cp16(&sKl[row * 72 + q8], kl + row * 64 + q8, true);
    }
    asm volatile("cp.async.commit_group;");
    asm volatile("cp.async.wait_group 0;");
    __syncthreads();

    float acc[2][8][4];
#pragma unroll
    for (int a = 0; a < 2; a++)
#pragma unroll
        for (int b = 0; b < 8; b++)
#pragma unroll
            for (int c = 0; c < 4; c++) acc[a][b][c] = 0.f;

#pragma unroll
    for (int ks = 0; ks < 64; ks += 16) {
        uint32_t ah[2][4], al[2][4];
#pragma unroll
        for (int mt = 0; mt < 2; mt++) {
            int rb = wm * 32 + mt * 16 + (lane & 15);
            int kc = ks + ((lane >> 4) << 3);
            LDSM4(ah[mt], s2u(&sQh[rb * 72 + kc]));
            LDSM4(al[mt], s2u(&sQl[rb * 72 + kc]));
        }
        int g = lane >> 3, l8 = lane & 7;
#pragma unroll
        for (int np = 0; np < 4; np++) {
            int nb = wn * 64 + np * 16;
            uint32_t bh[4], bl[4];
            int nr = nb + ((g >> 1) << 3) + l8;
            int kc = ks + ((g & 1) << 3);
            LDSM4(bh, s2u(&sKh[nr * 72 + kc]));
            LDSM4(bl, s2u(&sKl[nr * 72 + kc]));
#pragma unroll
            for (int mt = 0; mt < 2; mt++) {
#pragma unroll
                for (int j = 0; j < 2; j++) {
                    float* ac = acc[mt][np * 2 + j];
                    MMA_BF16(ac, ah[mt], bh[2 * j], bh[2 * j + 1]);
                    MMA_BF16(ac, ah[mt], bl[2 * j], bl[2 * j + 1]);
                    MMA_BF16(ac, al[mt], bh[2 * j], bh[2 * j + 1]);
                }
            }
        }
    }

    const float* qrb = g_qr + (size_t)bn * QL * RL;
#pragma unroll
    for (int mt = 0; mt < 2; mt++) {
#pragma unroll
        for (int np = 0; np < 4; np++) {
#pragma unroll
            for (int j = 0; j < 2; j++) {
                int col = j0 + wn * 64 + np * 16 + j * 8 + (lane & 3) * 2;
                int rb = i0 + wm * 32 + mt * 16 + (lane >> 2);
#pragma unroll
                for (int hh = 0; hh < 2; hh++) {
                    int r = rb + hh * 8;
                    float v0, v1;
                    if (col > r) v0 = -INFINITY;
                    else v0 = (acc[mt][np * 2 + j][hh * 2] +
                               qrb[(size_t)r * RL + (QL + col - r)]) * ATT_SCALE;
                    if (col + 1 > r) v1 = -INFINITY;
                    else v1 = (acc[mt][np * 2 + j][hh * 2 + 1] +
                               qrb[(size_t)r * RL + (QL + col + 1 - r)]) * ATT_SCALE;
                    *(float2*)&srow[(size_t)r * QL + col] = make_float2(v0, v1);
                }
            }
        }
    }
}

// ---------------------------------------------------------------------------
// Row softmax over key dim; writes SPLIT bf16 probabilities
// ---------------------------------------------------------------------------
__global__ __launch_bounds__(256) void k_softmax() {
    size_t row = blockIdx.x;
    const float* p = g_score + row * QL;
    int tid = threadIdx.x;
    float2 v = *(const float2*)(p + tid * 2);
    __shared__ float red[256];
    red[tid] = fmaxf(v.x, v.y);
    __syncthreads();
    for (int st = 128; st > 0; st >>= 1) {
        if (tid < st) red[tid] = fmaxf(red[tid], red[tid + st]);
        __syncthreads();
    }
    float mx = red[0];
    __syncthreads();
    float e0 = expf(v.x - mx), e1 = expf(v.y - mx);
    red[tid] = e0 + e1;
    __syncthreads();
    for (int st = 128; st > 0; st >>= 1) {
        if (tid < st) red[tid] += red[tid + st];
        __syncthreads();
    }
    float inv = 1.f / red[0];
    float p0 = e0 * inv, p1 = e1 * inv;
    __nv_bfloat16 h0, h1, l0, l1;
    split1(p0, h0, l0);
    split1(p1, h1, l1);
    *(__nv_bfloat162*)(g_ph + row * QL + tid * 2) = __nv_bfloat162(h0, h1);
    *(__nv_bfloat162*)(g_pl + row * QL + tid * 2) = __nv_bfloat162(l0, l1);
}

// ---------------------------------------------------------------------------
// vec = prob @ V (tensor core, NN). 128-row tiles, causal K bound.
// grid (4, 128). Writes split attn-out for Wo GEMM.
// ---------------------------------------------------------------------------
__global__ __launch_bounds__(256) void k_avmma() {
    int bn = blockIdx.y, b = bn >> 4, n = bn & 15;
    int i0 = blockIdx.x << 7;
    extern __shared__ __nv_bfloat16 sm[];
    __nv_bfloat16 *sPh = sm, *sPl = sm + 128 * 72, *sVh = sm + 2 * 128 * 72,
                  *sVl = sm + 2 * 128 * 72 + 64 * 72;
    int tid = threadIdx.x, lane = tid & 31, warp = tid >> 5;
    int wm = warp >> 1, wn = warp & 1;

    float acc[2][4][4];
#pragma unroll
    for (int a = 0; a < 2; a++)
#pragma unroll
        for (int bq = 0; bq < 4; bq++)
#pragma unroll
            for (int c = 0; c < 4; c++) acc[a][bq][c] = 0.f;

    const __nv_bfloat16* phb = g_ph + ((size_t)bn * QL + i0) * QL;
    const __nv_bfloat16* plb = g_pl + ((size_t)bn * QL + i0) * QL;
    const __nv_bfloat16* uh = g_uh + (size_t)bn * QL * DHD;
    const __nv_bfloat16* ul = g_ul + (size_t)bn * QL * DHD;

    int nchunks = (i0 >> 6) + 2;
    for (int cch = 0; cch < nchunks; cch++) {
        int jb = cch << 6;
#pragma unroll
        for (int u = 0; u < 4; u++) {
            int p = tid + u * 256;
            int row = p >> 3, q8 = (p & 7) << 3;
            cp16(&sPh[row * 72 + q8], phb + (size_t)row * QL + jb + q8, true);
            cp16(&sPl[row * 72 + q8], plb + (size_t)row * QL + jb + q8, true);
        }
#pragma unroll
        for (int u = 0; u < 2; u++) {
            int p = tid + u * 256;
            int row = p >> 3, q8 = (p & 7) << 3;
            cp16(&sVh[row * 72 + q8], uh + (size_t)(jb + row) * 64 + q8, true);
            cp16(&sVl[row * 72 + q8], ul + (size_t)(jb + row) * 64 + q8, true);
        }
        asm volatile("cp.async.commit_group;");
        asm volatile("cp.async.wait_group 0;");
        __syncthreads();

#pragma unroll
        for (int ks = 0; ks < 64; ks += 16) {
            uint32_t ah[2][4], al[2][4];
#pragma unroll
            for (int mt = 0; mt < 2; mt++) {
                int rb = wm * 32 + mt * 16 + (lane & 15);
                int kc = ks + ((lane >> 4) << 3);
                LDSM4(ah[mt], s2u(&sPh[rb * 72 + kc]));
                LDSM4(al[mt], s2u(&sPl[rb * 72 + kc]));
            }
            int g = lane >> 3, l8 = lane & 7;
#pragma unroll
            for (int np = 0; np < 2; np++) {
                int nb = wn * 32 + np * 16;
                uint32_t bh[4], bl[4];
                int kr = ks + ((g & 1) << 3) + l8;
                int nc = nb + ((g >> 1) << 3);
                LDSM4T(bh, s2u(&sVh[kr * 72 + nc]));
                LDSM4T(bl, s2u(&sVl[kr * 72 + nc]));
#pragma unroll
                for (int mt = 0; mt < 2; mt++) {
#pragma unroll
                    for (int j = 0; j < 2; j++) {
                        float* ac = acc[mt][np * 2 + j];
                        MMA_BF16(ac, ah[mt], bh[2 * j], bh[2 * j + 1]);
                        MMA_BF16(ac, ah[mt], bl[2 * j], bl[2 * j + 1]);
                        MMA_BF16(ac, al[mt], bh[2 * j], bh[2 * j + 1]);
                    }
                }
            }
        }
        __syncthreads();
    }

#pragma unroll
    for (int mt = 0; mt < 2; mt++) {
#pragma unroll
        for (int np = 0; np < 2; np++) {
#pragma unroll
            for (int j = 0; j < 2; j++) {
                int d = wn * 32 + np * 16 + j * 8 + (lane & 3) * 2;
                int rb = i0 + wm * 32 + mt * 16 + (lane >> 2);
#pragma unroll
                for (int hh = 0; hh < 2; hh++) {
                    int i = rb + hh * 8;
                    size_t o = ((size_t)i * BS + b) * DM + n * DHD + d;
                    float v0 = acc[mt][np * 2 + j][hh * 2];
                    float v1 = acc[mt][np * 2 + j][hh * 2 + 1];
                    __nv_bfloat16 h0, h1, l0, l1;
                    split1(v0, h0, l0);
                    split1(v1, h1, l1);
                    *(__nv_bfloat162*)(g_vh + o) = __nv_bfloat162(h0, h1);
                    *(__nv_bfloat162*)(g_vl + o) = __nv_bfloat162(l0, l1);
                }
            }
        }
    }
}

// ---------------------------------------------------------------------------
// O = LayerNorm(A + B) * gamma + beta; optional fused split outputs
// ---------------------------------------------------------------------------
__global__ __launch_bounds__(256) void k_lnres(const float* __restrict__ A,
                                               const float* __restrict__ Bi,
                                               const float* __restrict__ G,
                                               const float* __restrict__ Be,
                                               float* __restrict__ O,
                                               __nv_bfloat16* __restrict__ Oh,
                                               __nv_bfloat16* __restrict__ Ol) {
    int row = blockIdx.x, tid = threadIdx.x;
    size_t base = (size_t)row * DM + tid * 4;
    float4 va = *(const float4*)(A + base);
    float4 vb = *(const float4*)(Bi + base);
    float x[4] = {va.x + vb.x, va.y + vb.y, va.z + vb.z, va.w + vb.w};
    float s = x[0] + x[1] + x[2] + x[3];
    float s2 = x[0] * x[0] + x[1] * x[1] + x[2] * x[2] + x[3] * x[3];
    __shared__ float rs[256], rs2[256];
    rs[tid] = s;
    rs2[tid] = s2;
    __syncthreads();
    for (int st = 128; st > 0; st >>= 1) {
        if (tid < st) { rs[tid] += rs[tid + st]; rs2[tid] += rs2[tid + st]; }
        __syncthreads();
    }
    float mean = rs[0] * (1.f / (float)DM);
    float var = rs2[0] * (1.f / (float)DM) - mean * mean;
    float inv = rsqrtf(var + 1e-5f);
    float4 g4 = *(const float4*)(G + tid * 4);
    float4 b4 = *(const float4*)(Be + tid * 4);
    float y[4];
    y[0] = (x[0] - mean) * inv * g4.x + b4.x;
    y[1] = (x[1] - mean) * inv * g4.y + b4.y;
    y[2] = (x[2] - mean) * inv * g4.z + b4.z;
    y[3] = (x[3] - mean) * inv * g4.w + b4.w;
    *(float4*)(O + base) = make_float4(y[0], y[1], y[2], y[3]);
    if (Oh) split_store4(y[0], y[1], y[2], y[3], Oh + base, Ol + base);
}

// ---------------------------------------------------------------------------
// Launch sequence
// ---------------------------------------------------------------------------
extern "C" void kernel_launch(void* const* d_in, const int* in_sizes, int n_in,
                              void* d_out, int out_size) {
    const int*   src   = (const int*)d_in[0];
    const float* emb   = (const float*)d_in[1];
    const float* dec_b = (const float*)d_in[2];
    const float* Wqkv  = (const float*)d_in[3];
    const float* Wo    = (const float*)d_in[4];
    const float* ln0_g = (const float*)d_in[5];
    const float* ln0_b = (const float*)d_in[6];
    const float* W1    = (const float*)d_in[7];
    const float* b1    = (const float*)d_in[8];
    const float* W2    = (const float*)d_in[9];
    const float* b2    = (const float*)d_in[10];
    const float* ln1_g = (const float*)d_in[11];
    const float* ln1_b = (const float*)d_in[12];
    const float* ln2_g = (const float*)d_in[13];
    const float* ln2_b = (const float*)d_in[14];
    float* out = (float*)d_out;

    float *core, *big, *vec, *tmp, *h, *r, *rqkv;
    cudaGetSymbolAddress((void**)&core, g_core);
    cudaGetSymbolAddress((void**)&big,  g_big);
    cudaGetSymbolAddress((void**)&vec,  g_vec);
    cudaGetSymbolAddress((void**)&tmp,  g_tmp);
    cudaGetSymbolAddress((void**)&h,    g_h);
    cudaGetSymbolAddress((void**)&r,    g_r);
    cudaGetSymbolAddress((void**)&rqkv, g_rqkv);
    __nv_bfloat16 *ah, *al, *wh, *wl, *eh, *el, *ch, *cl, *vh, *vl, *hsh, *hsl;
    cudaGetSymbolAddress((void**)&ah,  g_ah);
    cudaGetSymbolAddress((void**)&al,  g_al);
    cudaGetSymbolAddress((void**)&wh,  g_wh);
    cudaGetSymbolAddress((void**)&wl,  g_wl);
    cudaGetSymbolAddress((void**)&eh,  g_eh);
    cudaGetSymbolAddress((void**)&el,  g_el);
    cudaGetSymbolAddress((void**)&ch,  g_ch);
    cudaGetSymbolAddress((void**)&cl,  g_cl);
    cudaGetSymbolAddress((void**)&vh,  g_vh);
    cudaGetSymbolAddress((void**)&vl,  g_vl);
    cudaGetSymbolAddress((void**)&hsh, g_hsh);
    cudaGetSymbolAddress((void**)&hsl, g_hsl);

    const int SMEM_NN = 75776, SMEM_NT = 81920;
    const int SMEM_ATT = 4 * 128 * 72 * 2;          // 73728
    const int SMEM_AV  = (2 * 128 + 2 * 64) * 72 * 2;  // 55296
    cudaFuncSetAttribute(k_mgemm<0, false, false>,
                         cudaFuncAttributeMaxDynamicSharedMemorySize, SMEM_NN);
    cudaFuncSetAttribute(k_mgemm<1, false, true>,
                         cudaFuncAttributeMaxDynamicSharedMemorySize, SMEM_NN);
    cudaFuncSetAttribute(k_mgemm<0, true, false>,
                         cudaFuncAttributeMaxDynamicSharedMemorySize, SMEM_NT);
    cudaFuncSetAttribute(k_qrmma, cudaFuncAttributeMaxDynamicSharedMemorySize, SMEM_ATT);
    cudaFuncSetAttribute(k_scoremma, cudaFuncAttributeMaxDynamicSharedMemorySize, SMEM_ATT);
    cudaFuncSetAttribute(k_avmma, cudaFuncAttributeMaxDynamicSharedMemorySize, SMEM_AV);

    auto split = [](const float* x, __nv_bfloat16* hh, __nv_bfloat16* ll, size_t n) {
        k_split<<<(unsigned)((n + 1023) / 1024), 256>>>(x, hh, ll, (int)n);
    };

    k_embed<<<TOK, 256>>>(src, emb);
    k_posemb<<<RL, 256>>>();
    split(emb, eh, el, (size_t)VC * DM);

    for (int l = 0; l < NL; l++) {
        const float* Wq = Wqkv + (size_t)l * DM * 3 * DM;
        // r split (hsh/hsl free until LN1 later this layer)
        split(r, hsh, hsl, (size_t)RL * DM);
        split(Wq, wh, wl, (size_t)DM * 3 * DM);
        // rqkv = r @ Wqkv[l]  (needed before qkvprep for rq_last)
        k_mgemm<0, false, false><<<dim3(3 * DM / 128, (RL + 127) / 128), 256, SMEM_NN>>>(
            hsh, hsl, wh, wl, nullptr, rqkv, nullptr, nullptr, RL, 3 * DM, DM);
        // qkv = core @ Wqkv[l]
        k_mgemm<0, false, false><<<dim3(3 * DM / 128, TOK / 128), 256, SMEM_NN>>>(
            ch, cl, wh, wl, nullptr, big, nullptr, nullptr, TOK, 3 * DM, DM);
        // per-head split operands
        k_rkprep<<<(RL * DM / 4 + 255) / 256, 256>>>();
        k_qkvprep<<<TOK * 3 * DM / 4 / 256, 256>>>();
        // attention (tensor core)
        k_qrmma<<<dim3(5, 4, BH), 256, SMEM_ATT>>>();
        k_scoremma<<<dim3(4, 4, BH), 256, SMEM_ATT>>>();
        k_softmax<<<BH * QL, 256>>>();
        k_avmma<<<dim3(4, BH), 256, SMEM_AV>>>();
        // attn_out = vec @ Wo[l]
        split(Wo + (size_t)l * DM * DM, wh, wl, (size_t)DM * DM);
        k_mgemm<0, false, false><<<dim3(DM / 128, TOK / 128), 256, SMEM_NN>>>(
            vh, vl, wh, wl, nullptr, tmp, nullptr, nullptr, TOK, DM, DM);
        // src2 = LN(core + attn_out); h = LN(core + src2) (+ split for FFN1)
        k_lnres<<<TOK, 256>>>(core, tmp, ln0_g + l * DM, ln0_b + l * DM, vec,
                              nullptr, nullptr);
        k_lnres<<<TOK, 256>>>(core, vec, ln1_g + l * DM, ln1_b + l * DM, h, hsh, hsl);
        // ffn hidden = gelu(h @ W1 + b1) -> split bf16 directly
        split(W1 + (size_t)l * DM * FFD, wh, wl, (size_t)DM * FFD);
        k_mgemm<1, false, true><<<dim3(FFD / 128, TOK / 128), 256, SMEM_NN>>>(
            hsh, hsl, wh, wl, b1 + (size_t)l * FFD, nullptr, ah, al, TOK, FFD, DM);
        // ffn out = hidden @ W2 + b2
        split(W2 + (size_t)l * FFD * DM, wh, wl, (size_t)FFD * DM);
        k_mgemm<0, false, false><<<dim3(DM / 128, TOK / 128), 256, SMEM_NN>>>(
            ah, al, wh, wl, b2 + (size_t)l * DM, tmp, nullptr, nullptr, TOK, DM, FFD);
        // core = LN(h + ffn) (+ split for next QKV / logits)
        k_lnres<<<TOK, 256>>>(h, tmp, ln2_g + l * DM, ln2_b + l * DM, core, ch, cl);
    }

    // logits = core @ emb^T + dec_b
    k_mgemm<0, true, false><<<dim3(VC / 128, TOK / 128), 256, SMEM_NT>>>(
        ch, cl, eh, el, dec_b, out, nullptr, nullptr, TOK, VC, DM);
}